// round 3
// baseline (speedup 1.0000x reference)
#include <cuda_runtime.h>

// Problem constants (fixed by the reference: N=8192, D=2048, M=512, E=4).
#define N_TOK 8192
#define D_DIM 2048
#define M_DIM 512
#define E_NUM 4

// GEMM tiling: 128x128 tile, K-step 16, 256 threads, 8x8 per-thread microtile.
#define BM 128
#define BN 128
#define BK 16
#define TPB 256
#define SPAD 4  // smem row padding (keeps rows 16B-aligned: (128+4)*4 = 528 = 33*16)

// Scratch (allocation-free rule: __device__ globals only).
__device__ int   g_cnt[E_NUM];
__device__ int   g_is64;               // 1 if domains is int64, 0 if int32
__device__ int   g_idx[E_NUM][N_TOK];
__device__ float g_h[(size_t)N_TOK * M_DIM];   // relu(x W1^T + b1), 16 MB

// ---------------------------------------------------------------------------
// Pass 0: reset counters + probe domains dtype.
// If domains were int64 with values in [0,4), every odd 32-bit word is 0.
// For int32 random values in [0,4), P(256 odd words all zero) = 4^-256 ~ 0.
// ---------------------------------------------------------------------------
__global__ void zero_kernel(const int* __restrict__ dom32) {
    if (threadIdx.x < E_NUM) g_cnt[threadIdx.x] = 0;
    __shared__ int any_nonzero;
    if (threadIdx.x == 0) any_nonzero = 0;
    __syncthreads();
    // scan odd words 1,3,...,511 (within bounds for both dtypes: >=8192 words)
    for (int w = 1 + 2 * threadIdx.x; w < 512; w += 2 * blockDim.x)
        if (dom32[w] != 0) any_nonzero = 1;
    __syncthreads();
    if (threadIdx.x == 0) g_is64 = (any_nonzero == 0) ? 1 : 0;
}

// ---------------------------------------------------------------------------
// Pass 1: bucket tokens by expert. Bucket order is nondeterministic (atomics)
// but every token's output depends only on its own row -> output deterministic.
// ---------------------------------------------------------------------------
__global__ void bucket_kernel(const void* __restrict__ domains) {
    int i = blockIdx.x * blockDim.x + threadIdx.x;
    if (i < N_TOK) {
        int e;
        if (g_is64) e = (int)((const long long*)domains)[i];
        else        e = ((const int*)domains)[i];
        e &= (E_NUM - 1);   // never fault; wrong dtype -> visible rel_err instead
        int pos = atomicAdd(&g_cnt[e], 1);
        g_idx[e][pos] = i;
    }
}

// ---------------------------------------------------------------------------
// Pass 2: grouped GEMM1  h[tok, m] = relu( sum_d x[tok,d] * W1[e,m,d] + b1[e,m] )
// A = gathered x rows [BM x BK], B = W1[e] rows [BN x BK]; both K-contiguous.
// ---------------------------------------------------------------------------
__global__ __launch_bounds__(TPB, 2) void gemm1_kernel(
    const float* __restrict__ x,
    const float* __restrict__ W1,
    const float* __restrict__ b1)
{
    const int e    = blockIdx.z;
    const int cnt  = g_cnt[e];
    const int row0 = blockIdx.x * BM;
    if (row0 >= cnt) return;
    const int col0 = blockIdx.y * BN;   // over M

    __shared__ float As[BK][BM + SPAD];
    __shared__ float Bs[BK][BN + SPAD];

    const int tid = threadIdx.x;
    const int tc  = tid & 15;   // 0..15 -> 8 output cols each
    const int tr  = tid >> 4;   // 0..15 -> 8 output rows each

    const int*   __restrict__ idx = g_idx[e];
    const float* __restrict__ We  = W1 + (size_t)e * M_DIM * D_DIM;

    // Pre-resolve the gathered token row for each of this thread's 2 A-load slots.
    int tokA[2];
    int rA[2], kcA[2];
#pragma unroll
    for (int j = 0; j < 2; j++) {
        int elem = tid + j * TPB;       // 0..511 float4 slots of the 128x16 tile
        rA[j]  = elem >> 2;             // 0..127
        kcA[j] = (elem & 3) << 2;       // 0,4,8,12
        int gi = row0 + rA[j];
        tokA[j] = idx[gi < cnt ? gi : (cnt - 1)];
    }

    float acc[8][8];
#pragma unroll
    for (int i = 0; i < 8; i++)
#pragma unroll
        for (int j = 0; j < 8; j++) acc[i][j] = 0.f;

    for (int k0 = 0; k0 < D_DIM; k0 += BK) {
#pragma unroll
        for (int j = 0; j < 2; j++) {
            const int r = rA[j], kc = kcA[j];
            float4 fa = *(const float4*)(x + (size_t)tokA[j] * D_DIM + k0 + kc);
            As[kc + 0][r] = fa.x; As[kc + 1][r] = fa.y;
            As[kc + 2][r] = fa.z; As[kc + 3][r] = fa.w;
            float4 fb = *(const float4*)(We + (size_t)(col0 + r) * D_DIM + k0 + kc);
            Bs[kc + 0][r] = fb.x; Bs[kc + 1][r] = fb.y;
            Bs[kc + 2][r] = fb.z; Bs[kc + 3][r] = fb.w;
        }
        __syncthreads();

#pragma unroll
        for (int k = 0; k < BK; k++) {
            float4 a0 = *(const float4*)&As[k][tr * 8];
            float4 a1 = *(const float4*)&As[k][tr * 8 + 4];
            float4 b0 = *(const float4*)&Bs[k][tc * 8];
            float4 b1v = *(const float4*)&Bs[k][tc * 8 + 4];
            float a[8] = {a0.x, a0.y, a0.z, a0.w, a1.x, a1.y, a1.z, a1.w};
            float b[8] = {b0.x, b0.y, b0.z, b0.w, b1v.x, b1v.y, b1v.z, b1v.w};
#pragma unroll
            for (int i = 0; i < 8; i++)
#pragma unroll
                for (int j2 = 0; j2 < 8; j2++)
                    acc[i][j2] = fmaf(a[i], b[j2], acc[i][j2]);
        }
        __syncthreads();
    }

    // Epilogue: bias + ReLU -> scratch h[tok, m]
#pragma unroll
    for (int i = 0; i < 8; i++) {
        int gi = row0 + tr * 8 + i;
        if (gi < cnt) {
            int tok = idx[gi];
            float* hp = g_h + (size_t)tok * M_DIM + col0 + tc * 8;
            const float* bp = b1 + (size_t)e * M_DIM + col0 + tc * 8;
#pragma unroll
            for (int j = 0; j < 8; j++) {
                float v = acc[i][j] + bp[j];
                hp[j] = v > 0.f ? v : 0.f;
            }
        }
    }
}

// ---------------------------------------------------------------------------
// Pass 3: grouped GEMM2  out[tok, d] = x[tok,d] + sum_m h[tok,m]*W2[e,d,m] + b2[e,d]
// ---------------------------------------------------------------------------
__global__ __launch_bounds__(TPB, 2) void gemm2_kernel(
    const float* __restrict__ x,
    const float* __restrict__ W2,
    const float* __restrict__ b2,
    float* __restrict__ out)
{
    const int e    = blockIdx.z;
    const int cnt  = g_cnt[e];
    const int row0 = blockIdx.x * BM;
    if (row0 >= cnt) return;
    const int col0 = blockIdx.y * BN;   // over D

    __shared__ float As[BK][BM + SPAD];
    __shared__ float Bs[BK][BN + SPAD];

    const int tid = threadIdx.x;
    const int tc  = tid & 15;
    const int tr  = tid >> 4;

    const int*   __restrict__ idx = g_idx[e];
    const float* __restrict__ We  = W2 + (size_t)e * D_DIM * M_DIM;

    int tokA[2];
    int rA[2], kcA[2];
#pragma unroll
    for (int j = 0; j < 2; j++) {
        int elem = tid + j * TPB;
        rA[j]  = elem >> 2;
        kcA[j] = (elem & 3) << 2;
        int gi = row0 + rA[j];
        tokA[j] = idx[gi < cnt ? gi : (cnt - 1)];
    }

    float acc[8][8];
#pragma unroll
    for (int i = 0; i < 8; i++)
#pragma unroll
        for (int j = 0; j < 8; j++) acc[i][j] = 0.f;

    for (int k0 = 0; k0 < M_DIM; k0 += BK) {
#pragma unroll
        for (int j = 0; j < 2; j++) {
            const int r = rA[j], kc = kcA[j];
            float4 fa = *(const float4*)(g_h + (size_t)tokA[j] * M_DIM + k0 + kc);
            As[kc + 0][r] = fa.x; As[kc + 1][r] = fa.y;
            As[kc + 2][r] = fa.z; As[kc + 3][r] = fa.w;
            float4 fb = *(const float4*)(We + (size_t)(col0 + r) * M_DIM + k0 + kc);
            Bs[kc + 0][r] = fb.x; Bs[kc + 1][r] = fb.y;
            Bs[kc + 2][r] = fb.z; Bs[kc + 3][r] = fb.w;
        }
        __syncthreads();

#pragma unroll
        for (int k = 0; k < BK; k++) {
            float4 a0 = *(const float4*)&As[k][tr * 8];
            float4 a1 = *(const float4*)&As[k][tr * 8 + 4];
            float4 b0 = *(const float4*)&Bs[k][tc * 8];
            float4 b1v = *(const float4*)&Bs[k][tc * 8 + 4];
            float a[8] = {a0.x, a0.y, a0.z, a0.w, a1.x, a1.y, a1.z, a1.w};
            float b[8] = {b0.x, b0.y, b0.z, b0.w, b1v.x, b1v.y, b1v.z, b1v.w};
#pragma unroll
            for (int i = 0; i < 8; i++)
#pragma unroll
                for (int j2 = 0; j2 < 8; j2++)
                    acc[i][j2] = fmaf(a[i], b[j2], acc[i][j2]);
        }
        __syncthreads();
    }

    // Epilogue: residual + bias -> out[tok, d]
#pragma unroll
    for (int i = 0; i < 8; i++) {
        int gi = row0 + tr * 8 + i;
        if (gi < cnt) {
            int tok = idx[gi];
            const float* xp = x   + (size_t)tok * D_DIM + col0 + tc * 8;
            float*       op = out + (size_t)tok * D_DIM + col0 + tc * 8;
            const float* bp = b2  + (size_t)e * D_DIM + col0 + tc * 8;
#pragma unroll
            for (int j = 0; j < 8; j++)
                op[j] = xp[j] + acc[i][j] + bp[j];
        }
    }
}

// ---------------------------------------------------------------------------
// Launch: 4 kernels, stream-ordered, graph-capturable (no sync, no alloc).
// Input order (metadata): x, domains, W1, b1, W2, b2. Output: float32 [N, D].
// ---------------------------------------------------------------------------
extern "C" void kernel_launch(void* const* d_in, const int* in_sizes, int n_in,
                              void* d_out, int out_size) {
    const float* x   = (const float*)d_in[0];
    const void*  dom = d_in[1];
    const float* W1  = (const float*)d_in[2];
    const float* b1  = (const float*)d_in[3];
    const float* W2  = (const float*)d_in[4];
    const float* b2  = (const float*)d_in[5];
    float*       out = (float*)d_out;

    zero_kernel<<<1, 256>>>((const int*)dom);
    bucket_kernel<<<N_TOK / 256, 256>>>(dom);

    dim3 g1(N_TOK / BM, M_DIM / BN, E_NUM);   // 64 x 4 x 4 (3/4 early-exit)
    gemm1_kernel<<<g1, TPB>>>(x, W1, b1);

    dim3 g2(N_TOK / BM, D_DIM / BN, E_NUM);   // 64 x 16 x 4
    gemm2_kernel<<<g2, TPB>>>(x, W2, b2, out);
}

// round 5
// speedup vs baseline: 1.9409x; 1.9409x over previous
#include <cuda_runtime.h>
#include <cuda_bf16.h>

// Problem constants
#define N_TOK 8192
#define D_DIM 2048
#define M_DIM 512
#define E_NUM 4
#define CAP   8704   // 128-aligned permuted-row capacity (8192 + 4*128)

// GEMM geometry
#define BK      32
#define SROW    80                       // padded smem row bytes (32 bf16 -> 80B stride)
#define PLANE   (128 * SROW)             // 10240 B per plane tile
#define STAGE   (4 * PLANE)              // Ahi, Alo, Bhi, Blo
#define DSMEM   (2 * STAGE)              // 81920 B double-buffered

// ---------------------------------------------------------------------------
// Device scratch (allocation-free rule: __device__ globals only)
// ---------------------------------------------------------------------------
__device__ int g_cnt[E_NUM];
__device__ int g_c2[E_NUM];
__device__ int g_off[E_NUM + 1];
__device__ int g_is64;
__device__ int g_ptok[CAP];

__device__ __align__(256) __nv_bfloat16 g_xhi[(size_t)CAP * D_DIM];
__device__ __align__(256) __nv_bfloat16 g_xlo[(size_t)CAP * D_DIM];
__device__ __align__(256) __nv_bfloat16 g_w1hi[(size_t)E_NUM * M_DIM * D_DIM];
__device__ __align__(256) __nv_bfloat16 g_w1lo[(size_t)E_NUM * M_DIM * D_DIM];
__device__ __align__(256) __nv_bfloat16 g_w2hi[(size_t)E_NUM * D_DIM * M_DIM];
__device__ __align__(256) __nv_bfloat16 g_w2lo[(size_t)E_NUM * D_DIM * M_DIM];
__device__ __align__(256) __nv_bfloat16 g_hhi[(size_t)CAP * M_DIM];
__device__ __align__(256) __nv_bfloat16 g_hlo[(size_t)CAP * M_DIM];

// fp32 -> bf16 hi/lo split
__device__ __forceinline__ void split2(float v, unsigned short& hi, unsigned short& lo) {
    __nv_bfloat16 h = __float2bfloat16(v);
    __nv_bfloat16 l = __float2bfloat16(v - __bfloat162float(h));
    hi = __bfloat16_as_ushort(h);
    lo = __bfloat16_as_ushort(l);
}

__device__ __forceinline__ unsigned smem_to_u32(const void* p) {
    unsigned a;
    asm("{ .reg .u64 t; cvta.to.shared.u64 t, %1; cvt.u32.u64 %0, t; }" : "=r"(a) : "l"(p));
    return a;
}
__device__ __forceinline__ void cp16(unsigned dst, const void* src) {
    asm volatile("cp.async.cg.shared.global [%0], [%1], 16;" :: "r"(dst), "l"(src));
}
#define CP_COMMIT() asm volatile("cp.async.commit_group;" ::: "memory")
#define CP_WAIT1()  asm volatile("cp.async.wait_group 1;" ::: "memory")
#define CP_WAIT0()  asm volatile("cp.async.wait_group 0;" ::: "memory")

__device__ __forceinline__ void ldsm4(unsigned* r, unsigned addr) {
    asm volatile("ldmatrix.sync.aligned.m8n8.x4.shared.b16 {%0,%1,%2,%3}, [%4];"
                 : "=r"(r[0]), "=r"(r[1]), "=r"(r[2]), "=r"(r[3]) : "r"(addr));
}
__device__ __forceinline__ void mma16816(float* c, const unsigned* a, const unsigned* b) {
    asm volatile("mma.sync.aligned.m16n8k16.row.col.f32.bf16.bf16.f32 "
                 "{%0,%1,%2,%3},{%4,%5,%6,%7},{%8,%9},{%0,%1,%2,%3};"
                 : "+f"(c[0]), "+f"(c[1]), "+f"(c[2]), "+f"(c[3])
                 : "r"(a[0]), "r"(a[1]), "r"(a[2]), "r"(a[3]), "r"(b[0]), "r"(b[1]));
}

// ---------------------------------------------------------------------------
// Prep kernels
// ---------------------------------------------------------------------------
__global__ void prep0_kernel(const int* __restrict__ dom32) {
    int t = blockIdx.x * blockDim.x + threadIdx.x;
    if (t < CAP) g_ptok[t] = -1;
    if (t < E_NUM) { g_cnt[t] = 0; g_c2[t] = 0; }
    if (blockIdx.x == 0) {
        __shared__ int anynz;
        if (threadIdx.x == 0) anynz = 0;
        __syncthreads();
        for (int w = 1 + 2 * threadIdx.x; w < 512; w += 2 * blockDim.x)
            if (dom32[w] != 0) anynz = 1;
        __syncthreads();
        if (threadIdx.x == 0) g_is64 = (anynz == 0) ? 1 : 0;
    }
}
__device__ __forceinline__ int read_dom(const void* dom, int i) {
    int e = g_is64 ? (int)((const long long*)dom)[i] : ((const int*)dom)[i];
    return e & (E_NUM - 1);
}
__global__ void count_kernel(const void* __restrict__ dom) {
    int i = blockIdx.x * blockDim.x + threadIdx.x;
    if (i < N_TOK) atomicAdd(&g_cnt[read_dom(dom, i)], 1);
}
__global__ void offsets_kernel() {
    if (threadIdx.x == 0) {
        int off = 0;
        for (int e = 0; e < E_NUM; e++) {
            g_off[e] = off;
            off += ((g_cnt[e] + 127) / 128) * 128;
        }
        g_off[E_NUM] = off;
    }
}
__global__ void scatter_kernel(const void* __restrict__ dom) {
    int i = blockIdx.x * blockDim.x + threadIdx.x;
    if (i < N_TOK) {
        int e = read_dom(dom, i);
        int pos = g_off[e] + atomicAdd(&g_c2[e], 1);
        g_ptok[pos] = i;
    }
}

// Gather + convert x into permuted bf16 hi/lo planes (padding rows -> zeros)
__global__ void convert_x_kernel(const float* __restrict__ x) {
    int p = blockIdx.x;
    int t = threadIdx.x;  // 256 threads, 8 elems each
    uint4* dh = (uint4*)(g_xhi + (size_t)p * D_DIM);
    uint4* dl = (uint4*)(g_xlo + (size_t)p * D_DIM);
    int tok = g_ptok[p];
    if (tok < 0) {
        uint4 z = make_uint4(0, 0, 0, 0);
        dh[t] = z; dl[t] = z;
        return;
    }
    const float4* src = (const float4*)(x + (size_t)tok * D_DIM);
    float4 a = src[t * 2], b = src[t * 2 + 1];
    float v[8] = {a.x, a.y, a.z, a.w, b.x, b.y, b.z, b.w};
    unsigned hw[4], lw[4];
#pragma unroll
    for (int q = 0; q < 4; q++) {
        unsigned short h0, l0, h1, l1;
        split2(v[2 * q], h0, l0);
        split2(v[2 * q + 1], h1, l1);
        hw[q] = (unsigned)h0 | ((unsigned)h1 << 16);
        lw[q] = (unsigned)l0 | ((unsigned)l1 << 16);
    }
    dh[t] = make_uint4(hw[0], hw[1], hw[2], hw[3]);
    dl[t] = make_uint4(lw[0], lw[1], lw[2], lw[3]);
}

// Convert W1 and W2 into bf16 hi/lo planes (4 elems / thread)
__global__ void convert_w_kernel(const float* __restrict__ W1, const float* __restrict__ W2) {
    size_t i = (size_t)blockIdx.x * blockDim.x + threadIdx.x;
    const size_t n1 = (size_t)E_NUM * M_DIM * D_DIM / 4;
    const size_t n2 = (size_t)E_NUM * D_DIM * M_DIM / 4;
    const float4* src;
    uint2 *dh, *dl;
    size_t j;
    if (i < n1)           { src = (const float4*)W1; j = i;      dh = (uint2*)g_w1hi; dl = (uint2*)g_w1lo; }
    else if (i < n1 + n2) { src = (const float4*)W2; j = i - n1; dh = (uint2*)g_w2hi; dl = (uint2*)g_w2lo; }
    else return;
    float4 a = src[j];
    unsigned short h0, l0, h1, l1, h2, l2, h3, l3;
    split2(a.x, h0, l0); split2(a.y, h1, l1); split2(a.z, h2, l2); split2(a.w, h3, l3);
    dh[j] = make_uint2((unsigned)h0 | ((unsigned)h1 << 16), (unsigned)h2 | ((unsigned)h3 << 16));
    dl[j] = make_uint2((unsigned)l0 | ((unsigned)l1 << 16), (unsigned)l2 | ((unsigned)l3 << 16));
}

// ---------------------------------------------------------------------------
// Grouped GEMM via mma.sync bf16x3. 128x128 CTA tile, BK=32, double-buffered
// cp.async, 8 warps each computing 64x32 (4x4 m16n8k16 tiles, 3 products).
// ---------------------------------------------------------------------------
__device__ __forceinline__ void prefetch_stage(
    unsigned sbase, int stage,
    const __nv_bfloat16* __restrict__ Ah, const __nv_bfloat16* __restrict__ Al,
    const __nv_bfloat16* __restrict__ Bh, const __nv_bfloat16* __restrict__ Bl,
    int kchunk, int KS, int tid)
{
    const unsigned s0 = sbase + stage * STAGE;
    const __nv_bfloat16* srcs[4] = {Ah, Al, Bh, Bl};
#pragma unroll
    for (int pl = 0; pl < 4; pl++) {
        const __nv_bfloat16* sp = srcs[pl] + (size_t)kchunk * BK;
        unsigned d0 = s0 + pl * PLANE;
#pragma unroll
        for (int t = 0; t < 2; t++) {
            int idx = tid + t * 256;
            int row = idx >> 2, c = idx & 3;
            cp16(d0 + row * SROW + c * 16, sp + (size_t)row * KS + c * 8);
        }
    }
}

template <int WHICH>
__global__ __launch_bounds__(256, 1) void moe_gemm_kernel(
    const float* __restrict__ x,
    const float* __restrict__ b1,
    const float* __restrict__ b2,
    float* __restrict__ out)
{
    constexpr int KS = (WHICH == 1) ? D_DIM : M_DIM;
    constexpr int NC = KS / BK;
    constexpr int NCOL = (WHICH == 1) ? M_DIM : D_DIM;

    const int row0 = blockIdx.x * 128;
    if (row0 >= g_off[E_NUM]) return;
    int e = 0;
    while (e < E_NUM - 1 && row0 >= g_off[e + 1]) e++;
    const int col0 = blockIdx.y * 128;

    extern __shared__ char smem_raw[];
    const unsigned sbase = smem_to_u32(smem_raw);

    const int tid = threadIdx.x;
    const int wid = tid >> 5, lane = tid & 31;
    const int warp_m = wid >> 2, warp_n = wid & 3;

    const __nv_bfloat16 *Ahi, *Alo, *Bhi, *Blo;
    if (WHICH == 1) {
        Ahi = g_xhi + (size_t)row0 * KS;
        Alo = g_xlo + (size_t)row0 * KS;
        Bhi = g_w1hi + ((size_t)e * M_DIM + col0) * D_DIM;
        Blo = g_w1lo + ((size_t)e * M_DIM + col0) * D_DIM;
    } else {
        Ahi = g_hhi + (size_t)row0 * KS;
        Alo = g_hlo + (size_t)row0 * KS;
        Bhi = g_w2hi + ((size_t)e * D_DIM + col0) * M_DIM;
        Blo = g_w2lo + ((size_t)e * D_DIM + col0) * M_DIM;
    }

    float acc[4][4][4];
#pragma unroll
    for (int i = 0; i < 4; i++)
#pragma unroll
        for (int j = 0; j < 4; j++)
#pragma unroll
            for (int q = 0; q < 4; q++) acc[i][j][q] = 0.f;

    // ldmatrix lane address components
    const int a_row = warp_m * 64 + (lane & 7) + ((lane >> 3) & 1) * 8;
    const int a_kc0 = ((lane >> 4) & 1) * 8;
    const int b_row = warp_n * 32 + (lane & 7) + ((lane >> 4) & 1) * 8;
    const int b_kc0 = ((lane >> 3) & 1) * 8;

    prefetch_stage(sbase, 0, Ahi, Alo, Bhi, Blo, 0, KS, tid);
    CP_COMMIT();

    for (int c = 0; c < NC; c++) {
        if (c + 1 < NC) {
            prefetch_stage(sbase, (c + 1) & 1, Ahi, Alo, Bhi, Blo, c + 1, KS, tid);
            CP_COMMIT();
            CP_WAIT1();
        } else {
            CP_WAIT0();
        }
        __syncthreads();

        const unsigned S = sbase + (c & 1) * STAGE;
#pragma unroll
        for (int ks = 0; ks < 2; ks++) {
            unsigned a_hi[4][4], a_lo[4][4];
            const unsigned aoffb = (unsigned)(a_row * SROW + (ks * 16 + a_kc0) * 2);
#pragma unroll
            for (int mt = 0; mt < 4; mt++) {
                unsigned off = aoffb + mt * 16 * SROW;
                ldsm4(a_hi[mt], S + 0 * PLANE + off);
                ldsm4(a_lo[mt], S + 1 * PLANE + off);
            }
            unsigned b_hi[8], b_lo[8];
            const unsigned boffb = (unsigned)(b_row * SROW + (ks * 16 + b_kc0) * 2);
#pragma unroll
            for (int np = 0; np < 2; np++) {
                unsigned off = boffb + np * 16 * SROW;
                ldsm4(&b_hi[np * 4], S + 2 * PLANE + off);
                ldsm4(&b_lo[np * 4], S + 3 * PLANE + off);
            }
#pragma unroll
            for (int mt = 0; mt < 4; mt++)
#pragma unroll
                for (int nt = 0; nt < 4; nt++) {
                    const unsigned* bh = &b_hi[(nt >> 1) * 4 + (nt & 1) * 2];
                    const unsigned* bl = &b_lo[(nt >> 1) * 4 + (nt & 1) * 2];
                    mma16816(acc[mt][nt], a_hi[mt], bh);
                    mma16816(acc[mt][nt], a_hi[mt], bl);
                    mma16816(acc[mt][nt], a_lo[mt], bh);
                }
        }
        __syncthreads();
    }

    // Epilogue
#pragma unroll
    for (int mt = 0; mt < 4; mt++) {
        const int prow = row0 + warp_m * 64 + mt * 16 + (lane >> 2);
#pragma unroll
        for (int half = 0; half < 2; half++) {
            const int p = prow + half * 8;
#pragma unroll
            for (int nt = 0; nt < 4; nt++) {
                const int ncol = col0 + warp_n * 32 + nt * 8 + (lane & 3) * 2;
                float v0 = acc[mt][nt][half * 2 + 0];
                float v1 = acc[mt][nt][half * 2 + 1];
                if (WHICH == 1) {
                    const float* bs = b1 + (size_t)e * M_DIM + ncol;
                    v0 = fmaxf(v0 + bs[0], 0.f);
                    v1 = fmaxf(v1 + bs[1], 0.f);
                    unsigned short h0, l0, h1, l1;
                    split2(v0, h0, l0);
                    split2(v1, h1, l1);
                    *(unsigned*)(g_hhi + (size_t)p * M_DIM + ncol) =
                        (unsigned)h0 | ((unsigned)h1 << 16);
                    *(unsigned*)(g_hlo + (size_t)p * M_DIM + ncol) =
                        (unsigned)l0 | ((unsigned)l1 << 16);
                } else {
                    const int tok = g_ptok[p];
                    if (tok >= 0) {
                        const float* xs = x + (size_t)tok * D_DIM + ncol;
                        const float* bs = b2 + (size_t)e * D_DIM + ncol;
                        float2 o;
                        o.x = xs[0] + v0 + bs[0];
                        o.y = xs[1] + v1 + bs[1];
                        *(float2*)(out + (size_t)tok * D_DIM + ncol) = o;
                    }
                }
            }
        }
    }
    (void)NCOL;
}

// ---------------------------------------------------------------------------
// Launch
// ---------------------------------------------------------------------------
extern "C" void kernel_launch(void* const* d_in, const int* in_sizes, int n_in,
                              void* d_out, int out_size) {
    const float* x   = (const float*)d_in[0];
    const void*  dom = d_in[1];
    const float* W1  = (const float*)d_in[2];
    const float* b1  = (const float*)d_in[3];
    const float* W2  = (const float*)d_in[4];
    const float* b2  = (const float*)d_in[5];
    float*       out = (float*)d_out;

    cudaFuncSetAttribute(moe_gemm_kernel<1>, cudaFuncAttributeMaxDynamicSharedMemorySize, DSMEM);
    cudaFuncSetAttribute(moe_gemm_kernel<2>, cudaFuncAttributeMaxDynamicSharedMemorySize, DSMEM);

    prep0_kernel<<<(CAP + 255) / 256, 256>>>((const int*)dom);
    count_kernel<<<N_TOK / 256, 256>>>(dom);
    offsets_kernel<<<1, 32>>>();
    scatter_kernel<<<N_TOK / 256, 256>>>(dom);
    convert_x_kernel<<<CAP, 256>>>(x);
    {
        const size_t tot = (size_t)E_NUM * M_DIM * D_DIM / 4 * 2;  // W1 + W2 float4 units
        convert_w_kernel<<<(unsigned)((tot + 255) / 256), 256>>>(W1, W2);
    }
    moe_gemm_kernel<1><<<dim3(CAP / 128, M_DIM / 128), 256, DSMEM>>>(x, b1, b2, out);
    moe_gemm_kernel<2><<<dim3(CAP / 128, D_DIM / 128), 256, DSMEM>>>(x, b1, b2, out);
}